// round 1
// baseline (speedup 1.0000x reference)
#include <cuda_runtime.h>

#define B_ 4
#define C_ 64
#define H_ 64
#define W_ 64
#define HW 4096
#define CO 64

typedef unsigned long long u64;

// Scratch (no allocs allowed): channels-last x, and transposed weights [k][c][co]
__device__ float g_xt[B_ * H_ * W_ * C_];          // 4 MB
__device__ float g_wt[(9 + 25 + 49) * C_ * CO];    // 1.36 MB

// ---------------------------------------------------------------------------
// x[B,C,H,W] -> xt[B,H,W,C]  (tiled transpose in the (c,w) plane per (b,h))
// ---------------------------------------------------------------------------
__global__ void tx_kernel(const float* __restrict__ x) {
    __shared__ float t[64][65];
    int b = blockIdx.x >> 6;
    int h = blockIdx.x & 63;
    for (int i = threadIdx.x; i < 4096; i += 256) {
        int c = i >> 6, w = i & 63;
        t[w][c] = x[((b * 64 + c) * 64 + h) * 64 + w];   // coalesced read
    }
    __syncthreads();
    for (int i = threadIdx.x; i < 4096; i += 256) {
        int w = i >> 6, c = i & 63;
        g_xt[((b * 64 + h) * 64 + w) * 64 + c] = t[w][c]; // coalesced write
    }
}

// ---------------------------------------------------------------------------
// w[Co,C,kh,kw] -> wt[k][c][co]
// ---------------------------------------------------------------------------
__global__ void tw_kernel(const float* __restrict__ w, int wofs, int K) {
    int idx = blockIdx.x * 256 + threadIdx.x;
    int total = CO * C_ * K;
    if (idx < total) {
        int k  = idx % K;
        int c  = (idx / K) % C_;
        int co = idx / (K * C_);
        g_wt[wofs + (k * C_ + c) * CO + co] = w[idx];
    }
}

// packed fp32x2 FMA (sm_100+ only; 2x fp32 throughput vs scalar FFMA)
__device__ __forceinline__ void ffma2(u64& d, u64 a, u64 b) {
    asm("fma.rn.f32x2 %0, %1, %2, %0;" : "+l"(d) : "l"(a), "l"(b));
}

// ---------------------------------------------------------------------------
// Fused DCNv2: 1 thread = 1 output pixel, 64 Co accumulators as 32 f32x2 regs.
// Grid = 384 CTAs x 128 thr: blocks [0,128) K=49, [128,256) K=25, [256,384) K=9
// ---------------------------------------------------------------------------
__global__ __launch_bounds__(128, 4) void dcn_kernel(
    const float* __restrict__ off1, const float* __restrict__ m1,
    const float* __restrict__ off2, const float* __restrict__ m2,
    const float* __restrict__ off3, const float* __restrict__ m3,
    float* __restrict__ out)
{
    __shared__ __align__(16) float swt[C_ * CO];   // 16 KB per-k weight slice

    int cb = blockIdx.x;
    int K, kw, pad, co0, wofs, pb;
    const float *off, *msk;
    if (cb < 128)      { K = 49; kw = 7; pad = 3; co0 = 128; wofs = 34 * 4096; off = off3; msk = m3; pb = cb;       }
    else if (cb < 256) { K = 25; kw = 5; pad = 2; co0 = 64;  wofs = 9 * 4096;  off = off2; msk = m2; pb = cb - 128; }
    else               { K = 9;  kw = 3; pad = 1; co0 = 0;   wofs = 0;         off = off1; msk = m1; pb = cb - 256; }

    int g  = pb * 128 + threadIdx.x;
    int xo = g & 63;
    int yo = (g >> 6) & 63;
    int b  = g >> 12;

    u64 acc[32];
#pragma unroll
    for (int i = 0; i < 32; ++i) acc[i] = 0ull;

    const float* offB = off + (size_t)b * 2 * K * HW + yo * 64 + xo;
    const float* mB   = msk + (size_t)b * K * HW + yo * 64 + xo;
    const float* xtB  = g_xt + (size_t)b * H_ * W_ * C_;
    const float* wtB  = g_wt + wofs;

    for (int k = 0; k < K; ++k) {
        __syncthreads();   // protect swt reads of previous iteration
        {
            const float4* src = (const float4*)(wtB + k * 4096);
            float4* dst = (float4*)swt;
            for (int i = threadIdx.x; i < 1024; i += 128) dst[i] = src[i];
        }
        __syncthreads();

        float dy = offB[(2 * k) * HW];
        float dx = offB[(2 * k + 1) * HW];
        float m  = mB[k * HW];
        int  ky  = k / kw;
        int  kx  = k - ky * kw;
        float py = (float)(yo - pad + ky) + dy;
        float px = (float)(xo - pad + kx) + dx;
        float fy = floorf(py), fx = floorf(px);
        float wy = py - fy,    wx = px - fx;
        int y0 = (int)fy, x0 = (int)fx;
        int y1 = y0 + 1,  x1 = x0 + 1;
        float vy0 = (y0 >= 0 && y0 < H_) ? 1.f : 0.f;
        float vy1 = (y1 >= 0 && y1 < H_) ? 1.f : 0.f;
        float vx0 = (x0 >= 0 && x0 < W_) ? 1.f : 0.f;
        float vx1 = (x1 >= 0 && x1 < W_) ? 1.f : 0.f;
        float w00 = (1.f - wy) * (1.f - wx) * m * vy0 * vx0;
        float w01 = (1.f - wy) * wx         * m * vy0 * vx1;
        float w10 = wy         * (1.f - wx) * m * vy1 * vx0;
        float w11 = wy         * wx         * m * vy1 * vx1;
        int cy0 = min(max(y0, 0), H_ - 1), cy1 = min(max(y1, 0), H_ - 1);
        int cx0 = min(max(x0, 0), W_ - 1), cx1 = min(max(x1, 0), W_ - 1);

        const float4* p00 = (const float4*)(xtB + (cy0 * 64 + cx0) * 64);
        const float4* p01 = (const float4*)(xtB + (cy0 * 64 + cx1) * 64);
        const float4* p10 = (const float4*)(xtB + (cy1 * 64 + cx0) * 64);
        const float4* p11 = (const float4*)(xtB + (cy1 * 64 + cx1) * 64);

#pragma unroll 4
        for (int c4 = 0; c4 < 16; ++c4) {
            float4 v00 = p00[c4], v01 = p01[c4], v10 = p10[c4], v11 = p11[c4];
            float s[4];
            s[0] = fmaf(w00, v00.x, fmaf(w01, v01.x, fmaf(w10, v10.x, w11 * v11.x)));
            s[1] = fmaf(w00, v00.y, fmaf(w01, v01.y, fmaf(w10, v10.y, w11 * v11.y)));
            s[2] = fmaf(w00, v00.z, fmaf(w01, v01.z, fmaf(w10, v10.z, w11 * v11.z)));
            s[3] = fmaf(w00, v00.w, fmaf(w01, v01.w, fmaf(w10, v10.w, w11 * v11.w)));
#pragma unroll
            for (int j = 0; j < 4; ++j) {
                u64 s2;
                asm("mov.b64 %0, {%1, %1};" : "=l"(s2) : "f"(s[j]));
                const longlong2* wr = (const longlong2*)(swt + (c4 * 4 + j) * CO);
#pragma unroll
                for (int q = 0; q < 16; ++q) {
                    longlong2 wv = wr[q];          // broadcast LDS.128: 4 weights (2x f32x2)
                    ffma2(acc[2 * q],     s2, (u64)wv.x);
                    ffma2(acc[2 * q + 1], s2, (u64)wv.y);
                }
            }
        }
    }

    // out[b][co0+co][yo][xo] — lanes vary xo -> fully coalesced per co
    float* outB = out + ((size_t)b * 192 + co0) * HW + yo * 64 + xo;
#pragma unroll
    for (int q = 0; q < 32; ++q) {
        unsigned lo = (unsigned)(acc[q] & 0xffffffffull);
        unsigned hi = (unsigned)(acc[q] >> 32);
        outB[(2 * q) * HW]     = __uint_as_float(lo);
        outB[(2 * q + 1) * HW] = __uint_as_float(hi);
    }
}

extern "C" void kernel_launch(void* const* d_in, const int* in_sizes, int n_in,
                              void* d_out, int out_size) {
    const float* x  = (const float*)d_in[0];
    const float* f1 = (const float*)d_in[1];
    const float* o1 = (const float*)d_in[2];
    const float* m1 = (const float*)d_in[3];
    const float* f2 = (const float*)d_in[4];
    const float* o2 = (const float*)d_in[5];
    const float* m2 = (const float*)d_in[6];
    const float* f3 = (const float*)d_in[7];
    const float* o3 = (const float*)d_in[8];
    const float* m3 = (const float*)d_in[9];
    float* out = (float*)d_out;

    tx_kernel<<<256, 256>>>(x);
    tw_kernel<<<(CO * C_ * 9  + 255) / 256, 256>>>(f1, 0,          9);
    tw_kernel<<<(CO * C_ * 25 + 255) / 256, 256>>>(f2, 9 * 4096,  25);
    tw_kernel<<<(CO * C_ * 49 + 255) / 256, 256>>>(f3, 34 * 4096, 49);
    dcn_kernel<<<384, 128>>>(o1, m1, o2, m2, o3, m3, out);
}

// round 2
// speedup vs baseline: 1.2136x; 1.2136x over previous
#include <cuda_runtime.h>

#define B_ 4
#define C_ 64
#define H_ 64
#define W_ 64
#define HW 4096
#define CO 64

typedef unsigned long long u64;

// ---------------- scratch (no allocs allowed) ----------------
__device__ float g_xt[B_ * H_ * W_ * C_];          // 4 MB channels-last x
__device__ float g_wt[(9 + 25 + 49) * C_ * CO];    // transposed weights [k][c][co]
__device__ int   g_q;                              // work-queue head
__device__ int   g_cnt[256];                       // arrival counters (128 conv3 + 128 conv2)
__device__ float g_p3[4 * 128 * 64 * 128];         // conv3 partials [seg][chunk][co][px]
__device__ float g_p2[2 * 128 * 64 * 128];         // conv2 partials

#define W2OFS (9 * 4096)
#define W3OFS (34 * 4096)

// ---------------------------------------------------------------------------
// prep: x transpose (blocks 0..255), counter reset (block 256),
//       weight transpose (blocks 257..1584)
// ---------------------------------------------------------------------------
__global__ void prep_kernel(const float* __restrict__ x,
                            const float* __restrict__ f1,
                            const float* __restrict__ f2,
                            const float* __restrict__ f3) {
    int blk = blockIdx.x;
    if (blk < 256) {
        __shared__ float t[64][65];
        int b = blk >> 6;
        int h = blk & 63;
        for (int i = threadIdx.x; i < 4096; i += 256) {
            int c = i >> 6, w = i & 63;
            t[w][c] = x[((b * 64 + c) * 64 + h) * 64 + w];
        }
        __syncthreads();
        for (int i = threadIdx.x; i < 4096; i += 256) {
            int w = i >> 6, c = i & 63;
            g_xt[((b * 64 + h) * 64 + w) * 64 + c] = t[w][c];
        }
    } else if (blk == 256) {
        if (threadIdx.x < 256) g_cnt[threadIdx.x] = 0;
        if (threadIdx.x == 0) g_q = 0;
    } else {
        int idx = (blk - 257) * 256 + threadIdx.x;
        // conv1: 64*64*9 = 36864, conv2: 102400, conv3: 200704 (total 339968)
        if (idx < 339968) {
            const float* w; int K, wofs, local;
            if (idx < 36864)       { w = f1; K = 9;  wofs = 0;      local = idx; }
            else if (idx < 139264) { w = f2; K = 25; wofs = W2OFS;  local = idx - 36864; }
            else                   { w = f3; K = 49; wofs = W3OFS;  local = idx - 139264; }
            int k  = local % K;
            int c  = (local / K) % C_;
            int co = local / (K * C_);
            g_wt[wofs + (k * C_ + c) * CO + co] = w[local];
        }
    }
}

// packed fp32x2 FMA (sm_100+; 2x fp32 throughput vs scalar FFMA)
__device__ __forceinline__ void ffma2(u64& d, u64 a, u64 b) {
    asm("fma.rn.f32x2 %0, %1, %2, %0;" : "+l"(d) : "l"(a), "l"(b));
}

// ---------------------------------------------------------------------------
// Persistent DCNv2. Work item = (conv, 128-pixel chunk, k-segment).
//   items 0..511   : conv3 (K=49), 4 segs {13,12,12,12}, chunk=i>>2, seg=i&3
//   items 512..767 : conv2 (K=25), 2 segs {13,12},       chunk=(i-512)>>1
//   items 768..895 : conv1 (K=9),  1 seg (direct write)
// Segments write partials; last-arriving segment CTA combines.
// ---------------------------------------------------------------------------
#define N_ITEMS 896

__global__ __launch_bounds__(128, 4) void dcn_kernel(
    const float* __restrict__ off1, const float* __restrict__ m1,
    const float* __restrict__ off2, const float* __restrict__ m2,
    const float* __restrict__ off3, const float* __restrict__ m3,
    float* __restrict__ out)
{
    __shared__ __align__(16) float swt[C_ * CO];   // 16 KB per-k weight slice
    __shared__ int s_item;
    __shared__ int s_last;

    for (;;) {
        __syncthreads();          // protect swt + s_item reuse across items
        if (threadIdx.x == 0) s_item = atomicAdd(&g_q, 1);
        __syncthreads();
        int item = s_item;
        if (item >= N_ITEMS) return;

        int K, kw, pad, co0, wofs, chunk, k0, klen, seg, nsegs, cidx;
        const float *off, *msk;
        float* pbase = 0;
        if (item < 512) {
            chunk = item >> 2; seg = item & 3;
            K = 49; kw = 7; pad = 3; co0 = 128; wofs = W3OFS;
            k0 = (seg == 0) ? 0 : (13 + 12 * (seg - 1));
            klen = (seg == 0) ? 13 : 12;
            nsegs = 4; cidx = chunk;
            off = off3; msk = m3;
            pbase = g_p3 + ((size_t)(seg * 128 + chunk)) * (64 * 128);
        } else if (item < 768) {
            int it = item - 512;
            chunk = it >> 1; seg = it & 1;
            K = 25; kw = 5; pad = 2; co0 = 64; wofs = W2OFS;
            k0 = (seg == 0) ? 0 : 13;
            klen = (seg == 0) ? 13 : 12;
            nsegs = 2; cidx = 128 + chunk;
            off = off2; msk = m2;
            pbase = g_p2 + ((size_t)(seg * 128 + chunk)) * (64 * 128);
        } else {
            chunk = item - 768; seg = 0;
            K = 9; kw = 3; pad = 1; co0 = 0; wofs = 0;
            k0 = 0; klen = 9; nsegs = 1; cidx = 0;
            off = off1; msk = m1;
        }

        int g  = chunk * 128 + threadIdx.x;
        int xo = g & 63;
        int yo = (g >> 6) & 63;
        int b  = g >> 12;

        u64 acc[32];
#pragma unroll
        for (int i = 0; i < 32; ++i) acc[i] = 0ull;

        const float* offB = off + (size_t)b * 2 * K * HW + yo * 64 + xo;
        const float* mB   = msk + (size_t)b * K * HW + yo * 64 + xo;
        const float* xtB  = g_xt + (size_t)b * H_ * W_ * C_;
        const float* wtB  = g_wt + wofs;

        for (int k = k0; k < k0 + klen; ++k) {
            __syncthreads();
            {
                const float4* src = (const float4*)(wtB + k * 4096);
                float4* dst = (float4*)swt;
                for (int i = threadIdx.x; i < 1024; i += 128) dst[i] = src[i];
            }
            __syncthreads();

            float dy = offB[(2 * k) * HW];
            float dx = offB[(2 * k + 1) * HW];
            float m  = mB[k * HW];
            int  ky  = k / kw;
            int  kx  = k - ky * kw;
            float py = (float)(yo - pad + ky) + dy;
            float px = (float)(xo - pad + kx) + dx;
            float fy = floorf(py), fx = floorf(px);
            float wy = py - fy,    wx = px - fx;
            int y0 = (int)fy, x0 = (int)fx;
            int y1 = y0 + 1,  x1 = x0 + 1;
            float vy0 = (y0 >= 0 && y0 < H_) ? 1.f : 0.f;
            float vy1 = (y1 >= 0 && y1 < H_) ? 1.f : 0.f;
            float vx0 = (x0 >= 0 && x0 < W_) ? 1.f : 0.f;
            float vx1 = (x1 >= 0 && x1 < W_) ? 1.f : 0.f;
            float w00 = (1.f - wy) * (1.f - wx) * m * vy0 * vx0;
            float w01 = (1.f - wy) * wx         * m * vy0 * vx1;
            float w10 = wy         * (1.f - wx) * m * vy1 * vx0;
            float w11 = wy         * wx         * m * vy1 * vx1;
            int cy0 = min(max(y0, 0), H_ - 1), cy1 = min(max(y1, 0), H_ - 1);
            int cx0 = min(max(x0, 0), W_ - 1), cx1 = min(max(x1, 0), W_ - 1);

            const float4* p00 = (const float4*)(xtB + (cy0 * 64 + cx0) * 64);
            const float4* p01 = (const float4*)(xtB + (cy0 * 64 + cx1) * 64);
            const float4* p10 = (const float4*)(xtB + (cy1 * 64 + cx0) * 64);
            const float4* p11 = (const float4*)(xtB + (cy1 * 64 + cx1) * 64);

#pragma unroll 4
            for (int c4 = 0; c4 < 16; ++c4) {
                float4 v00 = p00[c4], v01 = p01[c4], v10 = p10[c4], v11 = p11[c4];
                float s[4];
                s[0] = fmaf(w00, v00.x, fmaf(w01, v01.x, fmaf(w10, v10.x, w11 * v11.x)));
                s[1] = fmaf(w00, v00.y, fmaf(w01, v01.y, fmaf(w10, v10.y, w11 * v11.y)));
                s[2] = fmaf(w00, v00.z, fmaf(w01, v01.z, fmaf(w10, v10.z, w11 * v11.z)));
                s[3] = fmaf(w00, v00.w, fmaf(w01, v01.w, fmaf(w10, v10.w, w11 * v11.w)));
#pragma unroll
                for (int j = 0; j < 4; ++j) {
                    u64 s2;
                    asm("mov.b64 %0, {%1, %1};" : "=l"(s2) : "f"(s[j]));
                    const longlong2* wr = (const longlong2*)(swt + (c4 * 4 + j) * CO);
#pragma unroll
                    for (int q = 0; q < 16; ++q) {
                        longlong2 wv = wr[q];      // broadcast LDS.128
                        ffma2(acc[2 * q],     s2, (u64)wv.x);
                        ffma2(acc[2 * q + 1], s2, (u64)wv.y);
                    }
                }
            }
        }

        if (nsegs == 1) {
            // direct: out[b][co0+co][yo][xo]
            float* outB = out + ((size_t)b * 192 + co0) * HW + yo * 64 + xo;
#pragma unroll
            for (int q = 0; q < 32; ++q) {
                outB[(2 * q) * HW]     = __uint_as_float((unsigned)(acc[q] & 0xffffffffull));
                outB[(2 * q + 1) * HW] = __uint_as_float((unsigned)(acc[q] >> 32));
            }
        } else {
            // partial: pbase[co*128 + tid]
            float* pr = pbase + threadIdx.x;
#pragma unroll
            for (int q = 0; q < 32; ++q) {
                pr[(2 * q) * 128]     = __uint_as_float((unsigned)(acc[q] & 0xffffffffull));
                pr[(2 * q + 1) * 128] = __uint_as_float((unsigned)(acc[q] >> 32));
            }
            __threadfence();
            __syncthreads();
            if (threadIdx.x == 0)
                s_last = (atomicAdd(&g_cnt[cidx], 1) == nsegs - 1) ? 1 : 0;
            __syncthreads();
            if (s_last) {
                const float* base = (nsegs == 4) ? g_p3 : g_p2;
                float* outB = out + ((size_t)b * 192 + co0) * HW + yo * 64 + xo;
                for (int co = 0; co < 64; ++co) {
                    float s = 0.f;
                    for (int sg = 0; sg < nsegs; ++sg)
                        s += base[((size_t)(sg * 128 + chunk) * 64 + co) * 128 + threadIdx.x];
                    outB[co * HW] = s;
                }
            }
        }
    }
}

extern "C" void kernel_launch(void* const* d_in, const int* in_sizes, int n_in,
                              void* d_out, int out_size) {
    const float* x  = (const float*)d_in[0];
    const float* f1 = (const float*)d_in[1];
    const float* o1 = (const float*)d_in[2];
    const float* m1 = (const float*)d_in[3];
    const float* f2 = (const float*)d_in[4];
    const float* o2 = (const float*)d_in[5];
    const float* m2 = (const float*)d_in[6];
    const float* f3 = (const float*)d_in[7];
    const float* o3 = (const float*)d_in[8];
    const float* m3 = (const float*)d_in[9];
    float* out = (float*)d_out;

    prep_kernel<<<1585, 256>>>(x, f1, f2, f3);
    dcn_kernel<<<608, 128>>>(o1, m1, o2, m2, o3, m3, out);
}

// round 3
// speedup vs baseline: 1.7952x; 1.4793x over previous
#include <cuda_runtime.h>

#define HW 4096
typedef unsigned long long u64;

// ---------------- scratch (no allocs allowed) ----------------
__device__ float  g_xt[4 * 64 * 64 * 64];          // channels-last x [b][y][x][c]
__device__ float2 g_w2[(9 + 25 + 49) * 64 * 64];   // dup weights [k][c][co] -> {w,w}
__device__ int    g_q;
__device__ int    g_cnt[256];
__device__ float  g_p3[4 * 128 * 64 * 128];        // conv3 partials [seg][chunk][co][px]
__device__ float  g_p2[2 * 128 * 64 * 128];        // conv2 partials

#define W2OFS (9 * 4096)
#define W3OFS (34 * 4096)

// ---------------------------------------------------------------------------
__global__ void prep_kernel(const float* __restrict__ x,
                            const float* __restrict__ f1,
                            const float* __restrict__ f2,
                            const float* __restrict__ f3) {
    int blk = blockIdx.x;
    if (blk < 256) {
        __shared__ float t[64][65];
        int b = blk >> 6, h = blk & 63;
        for (int i = threadIdx.x; i < 4096; i += 256) {
            int c = i >> 6, w = i & 63;
            t[w][c] = x[((b * 64 + c) * 64 + h) * 64 + w];
        }
        __syncthreads();
        for (int i = threadIdx.x; i < 4096; i += 256) {
            int w = i >> 6, c = i & 63;
            g_xt[((b * 64 + h) * 64 + w) * 64 + c] = t[w][c];
        }
    } else if (blk == 256) {
        if (threadIdx.x < 256) g_cnt[threadIdx.x] = 0;
        if (threadIdx.x == 0) g_q = 0;
    } else {
        int idx = (blk - 257) * 256 + threadIdx.x;
        if (idx < 339968) {
            const float* w; int K, wofs, local;
            if (idx < 36864)       { w = f1; K = 9;  wofs = 0;     local = idx; }
            else if (idx < 139264) { w = f2; K = 25; wofs = W2OFS; local = idx - 36864; }
            else                   { w = f3; K = 49; wofs = W3OFS; local = idx - 139264; }
            int k  = local % K;
            int c  = (local / K) % 64;
            int co = local / (K * 64);
            float v = w[local];
            g_w2[wofs + (k * 64 + c) * 64 + co] = make_float2(v, v);
        }
    }
}

__device__ __forceinline__ void ffma2(u64& d, u64 a, u64 b) {
    asm("fma.rn.f32x2 %0, %1, %2, %0;" : "+l"(d) : "l"(a), "l"(b));
}

// ---------------------------------------------------------------------------
// Persistent DCNv2, two-phase per tap:
//   A: 16-lane groups gather one (px,corner) channel row coalesced -> samp[c][px]
//   B: 8px x 8co register-blocked GEMM, px-pair f32x2 accumulators
// Work item = (conv, 128-px chunk, k-segment); last-arrival combine for splits.
// ---------------------------------------------------------------------------
#define N_ITEMS 896

__global__ __launch_bounds__(128, 3) void dcn_kernel(
    const float* __restrict__ off1, const float* __restrict__ m1,
    const float* __restrict__ off2, const float* __restrict__ m2,
    const float* __restrict__ off3, const float* __restrict__ m3,
    float* __restrict__ out)
{
    __shared__ float samp[64 * 132];   // [c][px] row stride 132 (16B-aligned rows)
    __shared__ int s_item, s_last;

    const int tid  = threadIdx.x;
    const int lane = tid & 31;
    const int warp = tid >> 5;
    const int m    = lane & 15;        // c-granule in phase A
    const int gh   = lane >> 4;        // group half
    const int swzA = 8 * (m & 3);      // px swizzle for STS banking
    const int tpx  = tid & 15;         // phase B: px group
    const int tco  = tid >> 4;         // phase B: co group
    const int p8   = tpx * 8;
    const int co8  = tco * 8;

    for (;;) {
        __syncthreads();                       // samp + s_item reuse guard
        if (tid == 0) s_item = atomicAdd(&g_q, 1);
        __syncthreads();
        int item = s_item;
        if (item >= N_ITEMS) return;

        int K, kw, pad, co0, wofs, chunk, k0, klen, nsegs, cidx;
        const float *off, *msk;
        float* pbase = 0;
        if (item < 512) {
            chunk = item >> 2; int seg = item & 3;
            K = 49; kw = 7; pad = 3; co0 = 128; wofs = W3OFS;
            k0 = (seg == 0) ? 0 : (13 + 12 * (seg - 1));
            klen = (seg == 0) ? 13 : 12;
            nsegs = 4; cidx = chunk;
            off = off3; msk = m3;
            pbase = g_p3 + ((size_t)(seg * 128 + chunk)) * (64 * 128);
        } else if (item < 768) {
            int it = item - 512;
            chunk = it >> 1; int seg = it & 1;
            K = 25; kw = 5; pad = 2; co0 = 64; wofs = W2OFS;
            k0 = (seg == 0) ? 0 : 13;
            klen = (seg == 0) ? 13 : 12;
            nsegs = 2; cidx = 128 + chunk;
            off = off2; msk = m2;
            pbase = g_p2 + ((size_t)(seg * 128 + chunk)) * (64 * 128);
        } else {
            chunk = item - 768;
            K = 9; kw = 3; pad = 1; co0 = 0; wofs = 0;
            k0 = 0; klen = 9; nsegs = 1; cidx = 0;
            off = off1; msk = m1;
        }

        const int chunkPx0 = chunk * 128;
        const int b = chunkPx0 >> 12;
        const float* xtB = g_xt + (size_t)b * (64 * 64 * 64);

        u64 acc[4][8];
#pragma unroll
        for (int i = 0; i < 4; ++i)
#pragma unroll
            for (int j = 0; j < 8; ++j) acc[i][j] = 0ull;

        for (int k = k0; k < k0 + klen; ++k) {
            __syncthreads();   // samp reuse across taps
            // ---------------- phase A: sample into smem ----------------
            {
                const float* offY = off + ((size_t)(b * 2 * K + 2 * k)) * HW;
                const float* offX = offY + HW;
                const float* mk   = msk + ((size_t)(b * K + k)) * HW;
                const int ky = k / kw, kx = k - ky * kw;
                int pxt = warp * 32 + gh * 16;
                for (int it = 0; it < 16; ++it, ++pxt) {
                    int gpx = chunkPx0 + pxt;
                    int xo = gpx & 63, yo = (gpx >> 6) & 63;
                    int pix = yo * 64 + xo;
                    float dy = __ldg(offY + pix);
                    float dx = __ldg(offX + pix);
                    float mm = __ldg(mk + pix);
                    float py  = (float)(yo - pad + ky) + dy;
                    float pxx = (float)(xo - pad + kx) + dx;
                    float fy = floorf(py), fx = floorf(pxx);
                    float wy = py - fy,    wx = pxx - fx;
                    int y0 = (int)fy, x0 = (int)fx;
                    int y1 = y0 + 1,  x1 = x0 + 1;
                    float vy0 = (y0 >= 0 && y0 < 64) ? 1.f : 0.f;
                    float vy1 = (y1 >= 0 && y1 < 64) ? 1.f : 0.f;
                    float vx0 = (x0 >= 0 && x0 < 64) ? 1.f : 0.f;
                    float vx1 = (x1 >= 0 && x1 < 64) ? 1.f : 0.f;
                    float w00 = (1.f - wy) * (1.f - wx) * mm * vy0 * vx0;
                    float w01 = (1.f - wy) * wx         * mm * vy0 * vx1;
                    float w10 = wy         * (1.f - wx) * mm * vy1 * vx0;
                    float w11 = wy         * wx         * mm * vy1 * vx1;
                    int cy0 = min(max(y0, 0), 63), cy1 = min(max(y1, 0), 63);
                    int cx0 = min(max(x0, 0), 63), cx1 = min(max(x1, 0), 63);

                    const float4* r00 = (const float4*)(xtB + (cy0 * 64 + cx0) * 64);
                    const float4* r01 = (const float4*)(xtB + (cy0 * 64 + cx1) * 64);
                    const float4* r10 = (const float4*)(xtB + (cy1 * 64 + cx0) * 64);
                    const float4* r11 = (const float4*)(xtB + (cy1 * 64 + cx1) * 64);
                    float4 v00 = r00[m], v01 = r01[m], v10 = r10[m], v11 = r11[m];

                    float sx = fmaf(w00, v00.x, fmaf(w01, v01.x, fmaf(w10, v10.x, w11 * v11.x)));
                    float sy = fmaf(w00, v00.y, fmaf(w01, v01.y, fmaf(w10, v10.y, w11 * v11.y)));
                    float sz = fmaf(w00, v00.z, fmaf(w01, v01.z, fmaf(w10, v10.z, w11 * v11.z)));
                    float sw = fmaf(w00, v00.w, fmaf(w01, v01.w, fmaf(w10, v10.w, w11 * v11.w)));

                    int pxs = pxt ^ swzA;
                    float* dst = samp + (4 * m) * 132 + pxs;
                    dst[0]       = sx;
                    dst[132]     = sy;
                    dst[2 * 132] = sz;
                    dst[3 * 132] = sw;
                }
            }
            __syncthreads();
            // ---------------- phase B: 8px x 8co GEMM over c ----------------
            {
                const float2* wk = g_w2 + wofs + (size_t)k * 4096 + co8;
#pragma unroll 4
                for (int c = 0; c < 64; ++c) {
                    const float* srow = samp + c * 132 + (p8 ^ (8 * ((c >> 2) & 3)));
                    longlong2 sA = *(const longlong2*)(srow);
                    longlong2 sB = *(const longlong2*)(srow + 4);
                    u64 sp[4];
                    sp[0] = (u64)sA.x; sp[1] = (u64)sA.y;
                    sp[2] = (u64)sB.x; sp[3] = (u64)sB.y;
                    const ulonglong2* wr = (const ulonglong2*)(wk + (size_t)c * 64);
                    ulonglong2 wa = wr[0], wb = wr[1], wc_ = wr[2], wd = wr[3];
                    u64 wv[8];
                    wv[0] = wa.x; wv[1] = wa.y; wv[2] = wb.x; wv[3] = wb.y;
                    wv[4] = wc_.x; wv[5] = wc_.y; wv[6] = wd.x; wv[7] = wd.y;
#pragma unroll
                    for (int pp = 0; pp < 4; ++pp)
#pragma unroll
                        for (int j = 0; j < 8; ++j)
                            ffma2(acc[pp][j], sp[pp], wv[j]);
                }
            }
        }

        // ---------------- epilogue ----------------
        if (nsegs == 1) {
            float* ob = out + ((size_t)(b * 192 + co0 + co8)) * HW + ((chunkPx0 + p8) & 4095);
#pragma unroll
            for (int j = 0; j < 8; ++j)
#pragma unroll
                for (int pp = 0; pp < 4; ++pp)
                    *(float2*)(ob + (size_t)j * HW + 2 * pp) = *(float2*)&acc[pp][j];
        } else {
            float* pr = pbase + (co8) * 128 + p8;
#pragma unroll
            for (int j = 0; j < 8; ++j)
#pragma unroll
                for (int pp = 0; pp < 4; ++pp)
                    *(float2*)(pr + (size_t)j * 128 + 2 * pp) = *(float2*)&acc[pp][j];
            __threadfence();
            __syncthreads();
            if (tid == 0)
                s_last = (atomicAdd(&g_cnt[cidx], 1) == nsegs - 1) ? 1 : 0;
            __syncthreads();
            if (s_last) {
                const float* base = (nsegs == 4) ? g_p3 : g_p2;
                float* outB = out + ((size_t)(b * 192 + co0)) * HW + ((chunkPx0 + tid) & 4095);
                for (int co = 0; co < 64; ++co) {
                    float s = 0.f;
                    for (int sg = 0; sg < nsegs; ++sg)
                        s += base[((size_t)(sg * 128 + chunk) * 64 + co) * 128 + tid];
                    outB[(size_t)co * HW] = s;
                }
            }
        }
    }
}

extern "C" void kernel_launch(void* const* d_in, const int* in_sizes, int n_in,
                              void* d_out, int out_size) {
    const float* x  = (const float*)d_in[0];
    const float* f1 = (const float*)d_in[1];
    const float* o1 = (const float*)d_in[2];
    const float* m1 = (const float*)d_in[3];
    const float* f2 = (const float*)d_in[4];
    const float* o2 = (const float*)d_in[5];
    const float* m2 = (const float*)d_in[6];
    const float* f3 = (const float*)d_in[7];
    const float* o3 = (const float*)d_in[8];
    const float* m3 = (const float*)d_in[9];
    float* out = (float*)d_out;

    prep_kernel<<<1585, 256>>>(x, f1, f2, f3);
    dcn_kernel<<<444, 128>>>(o1, m1, o2, m2, o3, m3, out);
}

// round 5
// speedup vs baseline: 4.3781x; 2.4388x over previous
#include <cuda_runtime.h>
#include <cuda_bf16.h>

#define HW 4096
typedef unsigned int u32;

// ---------------- scratch (no allocs allowed) ----------------
__device__ __align__(16) float g_xt[4 * 64 * 64 * 64];           // channels-last x
__device__ __align__(16) unsigned short g_whimg[83 * 4096];      // per-tap 8KB swizzled W hi (bf16)
__device__ __align__(16) unsigned short g_wlimg[83 * 4096];      // per-tap 8KB swizzled W lo (bf16)
__device__ int   g_q;
__device__ int   g_cnt[256];
__device__ float g_p3[4 * 128 * 64 * 128];                       // conv3 partials [seg][chunk][co][px]
__device__ float g_p2[2 * 128 * 64 * 128];                       // conv2 partials

// ---------------------------------------------------------------------------
__global__ void prep_kernel(const float* __restrict__ x,
                            const float* __restrict__ f1,
                            const float* __restrict__ f2,
                            const float* __restrict__ f3) {
    int blk = blockIdx.x;
    if (blk < 256) {
        __shared__ float t[64][65];
        int b = blk >> 6, h = blk & 63;
        for (int i = threadIdx.x; i < 4096; i += 256) {
            int c = i >> 6, w = i & 63;
            t[w][c] = x[((b * 64 + c) * 64 + h) * 64 + w];
        }
        __syncthreads();
        for (int i = threadIdx.x; i < 4096; i += 256) {
            int w = i >> 6, c = i & 63;
            g_xt[((b * 64 + h) * 64 + w) * 64 + c] = t[w][c];
        }
    } else if (blk == 256) {
        if (threadIdx.x < 256) g_cnt[threadIdx.x] = 0;
        if (threadIdx.x == 0) g_q = 0;
    } else {
        int idx = (blk - 257) * 256 + threadIdx.x;
        if (idx < 339968) {
            const float* w; int K, t0, local;
            if (idx < 36864)       { w = f1; K = 9;  t0 = 0;  local = idx; }
            else if (idx < 139264) { w = f2; K = 25; t0 = 9;  local = idx - 36864; }
            else                   { w = f3; K = 49; t0 = 34; local = idx - 139264; }
            int k  = local % K;
            int c  = (local / K) & 63;
            int co = local / (K * 64);
            float v = w[local];
            __nv_bfloat16 h = __float2bfloat16(v);
            float hf = __bfloat162float(h);
            __nv_bfloat16 l = __float2bfloat16(v - hf);
            // byte offset in 8KB image: row=co (128B), swizzled column
            int boff = co * 128 + ((2 * c) ^ ((co & 7) << 4));
            int ui = (t0 + k) * 4096 + (boff >> 1);
            g_whimg[ui] = __bfloat16_as_ushort(h);
            g_wlimg[ui] = __bfloat16_as_ushort(l);
        }
    }
}

// ---------------- mma helpers (target-portable: sm_80 features) -------------
#define LDSM4(r, a) \
    asm volatile("ldmatrix.sync.aligned.m8n8.x4.shared.b16 {%0,%1,%2,%3}, [%4];" \
        : "=r"((r)[0]), "=r"((r)[1]), "=r"((r)[2]), "=r"((r)[3]) : "r"(a))

#define MMA16(d, a, b0, b1) \
    asm volatile("mma.sync.aligned.m16n8k16.row.col.f32.bf16.bf16.f32 " \
        "{%0,%1,%2,%3},{%4,%5,%6,%7},{%8,%9},{%0,%1,%2,%3};" \
        : "+f"((d)[0]), "+f"((d)[1]), "+f"((d)[2]), "+f"((d)[3]) \
        : "r"((a)[0]), "r"((a)[1]), "r"((a)[2]), "r"((a)[3]), "r"(b0), "r"(b1))

__device__ __forceinline__ u32 smem_u32(const void* p) {
    u32 a;
    asm("{ .reg .u64 t; cvta.to.shared.u64 t, %1; cvt.u32.u64 %0, t; }" : "=r"(a) : "l"(p));
    return a;
}

// ---------------------------------------------------------------------------
// Persistent DCNv2: sampling -> SMEM bf16 hi/lo, warp-level bf16 mma.sync GEMM
// with fp32 register accumulators persisting across taps of an item.
// Items: 0..511 conv3 (4 k-segs), 512..767 conv2 (2 segs), 768..895 conv1.
// ---------------------------------------------------------------------------
#define N_ITEMS 896
#define SH 0
#define SL 16384
#define WHOF 32768
#define WLOF 40960
#define CTRL 49152
#define SMEM_BYTES 49216

__global__ void __launch_bounds__(128, 3)
dcn_kernel(const float* __restrict__ off1, const float* __restrict__ m1,
           const float* __restrict__ off2, const float* __restrict__ m2,
           const float* __restrict__ off3, const float* __restrict__ m3,
           float* __restrict__ out)
{
    extern __shared__ char smem[];
    const u32 sb = smem_u32(smem);
    const int tid  = threadIdx.x;
    const int lane = tid & 31;
    const int wid  = tid >> 5;
    int* s_item = (int*)(smem + CTRL);
    int* s_last = (int*)(smem + CTRL + 4);

    // phase A ids
    const int hw_id = tid >> 4, m = tid & 15;
    // ldmatrix lane addressing (A: rows=px, B: rows=co), SW128-style xor swizzle
    const int rowA  = lane & 15;
    const int acol0 = (lane >> 4) << 4;                 // 0 or 16
    const int aswz  = (rowA & 7) << 4;
    const int rbA0  = (32 * wid + rowA) * 128;
    const int rbA1  = rbA0 + 16 * 128;
    const int rowB  = (lane & 7) + ((lane & 16) >> 1);  // 0..15
    const int bcol0 = (lane & 8) << 1;                  // 0 or 16
    const int bswz  = (rowB & 7) << 4;
    const int rbB   = rowB * 128;
    const int r4 = lane >> 2, c2 = 2 * (lane & 3);

    for (;;) {
        __syncthreads();
        if (tid == 0) *s_item = atomicAdd(&g_q, 1);
        __syncthreads();
        int item = *s_item;
        if (item >= N_ITEMS) return;

        int K, kw, pad, co0, wt0, chunk, k0, klen, seg, nsegs, cidx;
        const float *off, *msk;
        float* pbase = 0;
        if (item < 512) {
            chunk = item >> 2; seg = item & 3;
            K = 49; kw = 7; pad = 3; co0 = 128; wt0 = 34;
            k0 = (seg == 0) ? 0 : (13 + 12 * (seg - 1));
            klen = (seg == 0) ? 13 : 12;
            nsegs = 4; cidx = chunk;
            off = off3; msk = m3;
            pbase = g_p3 + ((size_t)(seg * 128 + chunk)) * (64 * 128);
        } else if (item < 768) {
            int it = item - 512;
            chunk = it >> 1; seg = it & 1;
            K = 25; kw = 5; pad = 2; co0 = 64; wt0 = 9;
            k0 = (seg == 0) ? 0 : 13;
            klen = (seg == 0) ? 13 : 12;
            nsegs = 2; cidx = 128 + chunk;
            off = off2; msk = m2;
            pbase = g_p2 + ((size_t)(seg * 128 + chunk)) * (64 * 128);
        } else {
            chunk = item - 768; seg = 0;
            K = 9; kw = 3; pad = 1; co0 = 0; wt0 = 0;
            k0 = 0; klen = 9; nsegs = 1; cidx = 0;
            off = off1; msk = m1;
        }

        const int chunkPx0 = chunk << 7;
        const int b = chunkPx0 >> 12;
        const float* xtB = g_xt + (size_t)b * (64 * 64 * 64);
        const int pixl = (chunkPx0 + hw_id * 16 + m) & 4095;
        const float* offB = off + (size_t)b * 2 * K * HW;
        const float* mskB = msk + (size_t)b * K * HW;

        float acc[2][8][4];
#pragma unroll
        for (int i = 0; i < 2; ++i)
#pragma unroll
            for (int j = 0; j < 8; ++j)
#pragma unroll
                for (int q = 0; q < 4; ++q) acc[i][j][q] = 0.f;

        for (int t = 0; t < klen; ++t) {
            const int k = k0 + t;
            __syncthreads();   // prev tap's mma done reading S/W

            // ---- W tile copy (16KB) ----
            {
                const uint4* srcH = (const uint4*)(g_whimg + (size_t)(wt0 + k) * 4096);
                const uint4* srcL = (const uint4*)(g_wlimg + (size_t)(wt0 + k) * 4096);
                uint4* dstH = (uint4*)(smem + WHOF);
                uint4* dstL = (uint4*)(smem + WLOF);
#pragma unroll
                for (int i = 0; i < 4; ++i) {
                    dstH[tid + 128 * i] = srcH[tid + 128 * i];
                    dstL[tid + 128 * i] = srcL[tid + 128 * i];
                }
            }
            // ---- sample S(k) -> SMEM (bf16 hi/lo) ----
            {
                const float* offY = offB + (size_t)(2 * k) * HW;
                const float* offX = offY + HW;
                const float* mk   = mskB + (size_t)k * HW;
                float dyr = __ldg(offY + pixl);
                float dxr = __ldg(offX + pixl);
                float mmr = __ldg(mk + pixl);
                const int ky = k / kw, kx = k - ky * kw;
#pragma unroll 4
                for (int it = 0; it < 16; ++it) {
                    float dy = __shfl_sync(0xffffffffu, dyr, (tid & 16) + it);
                    float dx = __shfl_sync(0xffffffffu, dxr, (tid & 16) + it);
                    float mm = __shfl_sync(0xffffffffu, mmr, (tid & 16) + it);
                    int px = hw_id * 16 + it;
                    int gpx = chunkPx0 + px;
                    int xo = gpx & 63, yo = (gpx >> 6) & 63;
                    float py  = (float)(yo - pad + ky) + dy;
                    float pxx = (float)(xo - pad + kx) + dx;
                    float fy = floorf(py), fx = floorf(pxx);
                    float wy = py - fy,    wx = pxx - fx;
                    int y0 = (int)fy, x0 = (int)fx;
                    int y1 = y0 + 1,  x1 = x0 + 1;
                    float vy0 = (y0 >= 0 && y0 < 64) ? 1.f : 0.f;
                    float vy1 = (y1 >= 0 && y1 < 64) ? 1.f : 0.f;
                    float vx0 = (x0 >= 0 && x0 < 64) ? 1.f : 0.f;
                    float vx1 = (x1 >= 0 && x1 < 64) ? 1.f : 0.f;
                    float w00 = (1.f - wy) * (1.f - wx) * mm * vy0 * vx0;
                    float w01 = (1.f - wy) * wx         * mm * vy0 * vx1;
                    float w10 = wy         * (1.f - wx) * mm * vy1 * vx0;
                    float w11 = wy         * wx         * mm * vy1 * vx1;
                    int cy0 = min(max(y0, 0), 63), cy1 = min(max(y1, 0), 63);
                    int cx0 = min(max(x0, 0), 63), cx1 = min(max(x1, 0), 63);
                    const float4* r00 = (const float4*)(xtB + (cy0 * 64 + cx0) * 64);
                    const float4* r01 = (const float4*)(xtB + (cy0 * 64 + cx1) * 64);
                    const float4* r10 = (const float4*)(xtB + (cy1 * 64 + cx0) * 64);
                    const float4* r11 = (const float4*)(xtB + (cy1 * 64 + cx1) * 64);
                    float4 v00 = r00[m], v01 = r01[m], v10 = r10[m], v11 = r11[m];

                    float s0 = fmaf(w00, v00.x, fmaf(w01, v01.x, fmaf(w10, v10.x, w11 * v11.x)));
                    float s1 = fmaf(w00, v00.y, fmaf(w01, v01.y, fmaf(w10, v10.y, w11 * v11.y)));
                    float s2 = fmaf(w00, v00.z, fmaf(w01, v01.z, fmaf(w10, v10.z, w11 * v11.z)));
                    float s3 = fmaf(w00, v00.w, fmaf(w01, v01.w, fmaf(w10, v10.w, w11 * v11.w)));

                    __nv_bfloat162 h01 = __floats2bfloat162_rn(s0, s1);
                    __nv_bfloat162 h23 = __floats2bfloat162_rn(s2, s3);
                    float2 f01 = __bfloat1622float2(h01);
                    float2 f23 = __bfloat1622float2(h23);
                    __nv_bfloat162 l01 = __floats2bfloat162_rn(s0 - f01.x, s1 - f01.y);
                    __nv_bfloat162 l23 = __floats2bfloat162_rn(s2 - f23.x, s3 - f23.y);

                    int cb = px * 128 + ((8 * m) ^ ((px & 7) << 4));
                    *(uint2*)(smem + SH + cb) =
                        make_uint2(*(u32*)&h01, *(u32*)&h23);
                    *(uint2*)(smem + SL + cb) =
                        make_uint2(*(u32*)&l01, *(u32*)&l23);
                }
            }
            __syncthreads();

            // ---- GEMM: 3-pass bf16 split, fp32 accum in registers ----
#pragma unroll
            for (int k4 = 0; k4 < 4; ++k4) {
                u32 colA = (u32)((32 * k4 + acol0) ^ aswz);
                u32 aH0[4], aH1[4], aL0[4], aL1[4];
                LDSM4(aH0, sb + SH + rbA0 + colA);
                LDSM4(aH1, sb + SH + rbA1 + colA);
                LDSM4(aL0, sb + SL + rbA0 + colA);
                LDSM4(aL1, sb + SL + rbA1 + colA);
                u32 colB = (u32)((32 * k4 + bcol0) ^ bswz);
#pragma unroll
                for (int p = 0; p < 4; ++p) {
                    u32 badr = (u32)(rbB + p * 2048) + colB;
                    u32 bH[4], bL[4];
                    LDSM4(bH, sb + WHOF + badr);
                    LDSM4(bL, sb + WLOF + badr);
                    MMA16(acc[0][2 * p],     aH0, bH[0], bH[1]);
                    MMA16(acc[1][2 * p],     aH1, bH[0], bH[1]);
                    MMA16(acc[0][2 * p + 1], aH0, bH[2], bH[3]);
                    MMA16(acc[1][2 * p + 1], aH1, bH[2], bH[3]);
                    MMA16(acc[0][2 * p],     aL0, bH[0], bH[1]);
                    MMA16(acc[1][2 * p],     aL1, bH[0], bH[1]);
                    MMA16(acc[0][2 * p + 1], aL0, bH[2], bH[3]);
                    MMA16(acc[1][2 * p + 1], aL1, bH[2], bH[3]);
                    MMA16(acc[0][2 * p],     aH0, bL[0], bL[1]);
                    MMA16(acc[1][2 * p],     aH1, bL[0], bL[1]);
                    MMA16(acc[0][2 * p + 1], aH0, bL[2], bL[3]);
                    MMA16(acc[1][2 * p + 1], aH1, bL[2], bL[3]);
                }
            }
        }

        // ---------------- epilogue ----------------
        if (nsegs == 1) {
            float* ob = out + (size_t)(b * 192 + co0) * HW;
#pragma unroll
            for (int mt = 0; mt < 2; ++mt) {
                int pxl = 32 * wid + 16 * mt + r4;
                int pix0 = (chunkPx0 + pxl) & 4095;
                int pix1 = (chunkPx0 + pxl + 8) & 4095;
#pragma unroll
                for (int nt = 0; nt < 8; ++nt) {
                    int co = 8 * nt + c2;
                    ob[(size_t)co * HW + pix0]       = acc[mt][nt][0];
                    ob[(size_t)(co + 1) * HW + pix0] = acc[mt][nt][1];
                    ob[(size_t)co * HW + pix1]       = acc[mt][nt][2];
                    ob[(size_t)(co + 1) * HW + pix1] = acc[mt][nt][3];
                }
            }
        } else {
#pragma unroll
            for (int mt = 0; mt < 2; ++mt) {
                int pxl = 32 * wid + 16 * mt + r4;
#pragma unroll
                for (int nt = 0; nt < 8; ++nt) {
                    int co = 8 * nt + c2;
                    pbase[co * 128 + pxl]           = acc[mt][nt][0];
                    pbase[(co + 1) * 128 + pxl]     = acc[mt][nt][1];
                    pbase[co * 128 + pxl + 8]       = acc[mt][nt][2];
                    pbase[(co + 1) * 128 + pxl + 8] = acc[mt][nt][3];
                }
            }
            __threadfence();
            __syncthreads();
            if (tid == 0)
                *s_last = (atomicAdd(&g_cnt[cidx], 1) == nsegs - 1) ? 1 : 0;
            __syncthreads();
            if (*s_last) {
                const float* basep = (nsegs == 4) ? g_p3 : g_p2;
                float* outB = out + (size_t)(b * 192 + co0) * HW + ((chunkPx0 + tid) & 4095);
                for (int co = 0; co < 64; ++co) {
                    float s = 0.f;
                    for (int sg = 0; sg < nsegs; ++sg)
                        s += basep[((size_t)(sg * 128 + chunk) * 64 + co) * 128 + tid];
                    outB[(size_t)co * HW] = s;
                }
            }
        }
    }
}

extern "C" void kernel_launch(void* const* d_in, const int* in_sizes, int n_in,
                              void* d_out, int out_size) {
    const float* x  = (const float*)d_in[0];
    const float* f1 = (const float*)d_in[1];
    const float* o1 = (const float*)d_in[2];
    const float* m1 = (const float*)d_in[3];
    const float* f2 = (const float*)d_in[4];
    const float* o2 = (const float*)d_in[5];
    const float* m2 = (const float*)d_in[6];
    const float* f3 = (const float*)d_in[7];
    const float* o3 = (const float*)d_in[8];
    const float* m3 = (const float*)d_in[9];
    float* out = (float*)d_out;

    cudaFuncSetAttribute(dcn_kernel, cudaFuncAttributeMaxDynamicSharedMemorySize, SMEM_BYTES);
    prep_kernel<<<1585, 256>>>(x, f1, f2, f3);
    dcn_kernel<<<444, 128, SMEM_BYTES>>>(o1, m1, o2, m2, o3, m3, out);
}

// round 6
// speedup vs baseline: 4.6725x; 1.0672x over previous
#include <cuda_runtime.h>
#include <cuda_bf16.h>

#define HW 4096
typedef unsigned int u32;

// ---------------- scratch (no allocs allowed) ----------------
__device__ __align__(16) float g_xt[4 * 64 * 64 * 64];           // channels-last x
__device__ __align__(16) unsigned short g_whimg[83 * 4096];      // per-tap 8KB swizzled W hi (bf16)
__device__ __align__(16) unsigned short g_wlimg[83 * 4096];      // per-tap 8KB swizzled W lo (bf16)
__device__ int   g_q;
__device__ int   g_cnt[256];
__device__ float g_p3[4 * 128 * 64 * 128];                       // conv3 partials [seg][chunk][co][px]
__device__ float g_p2[2 * 128 * 64 * 128];                       // conv2 partials

// ---------------------------------------------------------------------------
__global__ void prep_kernel(const float* __restrict__ x,
                            const float* __restrict__ f1,
                            const float* __restrict__ f2,
                            const float* __restrict__ f3) {
    int blk = blockIdx.x;
    if (blk < 256) {
        __shared__ float t[64][65];
        int b = blk >> 6, h = blk & 63;
        for (int i = threadIdx.x; i < 4096; i += 256) {
            int c = i >> 6, w = i & 63;
            t[w][c] = x[((b * 64 + c) * 64 + h) * 64 + w];
        }
        __syncthreads();
        for (int i = threadIdx.x; i < 4096; i += 256) {
            int w = i >> 6, c = i & 63;
            g_xt[((b * 64 + h) * 64 + w) * 64 + c] = t[w][c];
        }
    } else if (blk == 256) {
        if (threadIdx.x < 256) g_cnt[threadIdx.x] = 0;
        if (threadIdx.x == 0) g_q = 0;
    } else {
        int idx = (blk - 257) * 256 + threadIdx.x;
        if (idx < 339968) {
            const float* w; int K, t0, local;
            if (idx < 36864)       { w = f1; K = 9;  t0 = 0;  local = idx; }
            else if (idx < 139264) { w = f2; K = 25; t0 = 9;  local = idx - 36864; }
            else                   { w = f3; K = 49; t0 = 34; local = idx - 139264; }
            int k  = local % K;
            int c  = (local / K) & 63;
            int co = local / (K * 64);
            float v = w[local];
            __nv_bfloat16 h = __float2bfloat16(v);
            float hf = __bfloat162float(h);
            __nv_bfloat16 l = __float2bfloat16(v - hf);
            int boff = co * 128 + ((2 * c) ^ ((co & 7) << 4));
            int ui = (t0 + k) * 4096 + (boff >> 1);
            g_whimg[ui] = __bfloat16_as_ushort(h);
            g_wlimg[ui] = __bfloat16_as_ushort(l);
        }
    }
}

// ---------------- mma helpers (target-portable: sm_80 features) -------------
#define LDSM4(r, a) \
    asm volatile("ldmatrix.sync.aligned.m8n8.x4.shared.b16 {%0,%1,%2,%3}, [%4];" \
        : "=r"((r)[0]), "=r"((r)[1]), "=r"((r)[2]), "=r"((r)[3]) : "r"(a))

#define MMA16(d, a, b0, b1) \
    asm volatile("mma.sync.aligned.m16n8k16.row.col.f32.bf16.bf16.f32 " \
        "{%0,%1,%2,%3},{%4,%5,%6,%7},{%8,%9},{%0,%1,%2,%3};" \
        : "+f"((d)[0]), "+f"((d)[1]), "+f"((d)[2]), "+f"((d)[3]) \
        : "r"((a)[0]), "r"((a)[1]), "r"((a)[2]), "r"((a)[3]), "r"(b0), "r"(b1))

#define CPA16(dst, src) \
    asm volatile("cp.async.ca.shared.global [%0], [%1], 16;" :: "r"(dst), "l"(src))

__device__ __forceinline__ u32 smem_u32(const void* p) {
    u32 a;
    asm("{ .reg .u64 t; cvta.to.shared.u64 t, %1; cvt.u32.u64 %0, t; }" : "=r"(a) : "l"(p));
    return a;
}

// ---------------------------------------------------------------------------
// Persistent DCNv2: sampling -> SMEM bf16 hi/lo, warp-level bf16 mma.sync GEMM,
// fp32 register accumulators persist across taps of an item.
// Bilinear setup hoisted: computed once per thread (own px), broadcast by shfl.
// ---------------------------------------------------------------------------
#define N_ITEMS 896
#define SH 0
#define SL 16384
#define WHOF 32768
#define WLOF 40960
#define CTRL 49152
#define SMEM_BYTES 49216

__global__ void __launch_bounds__(128, 3)
dcn_kernel(const float* __restrict__ off1, const float* __restrict__ m1,
           const float* __restrict__ off2, const float* __restrict__ m2,
           const float* __restrict__ off3, const float* __restrict__ m3,
           float* __restrict__ out)
{
    extern __shared__ char smem[];
    const u32 sb = smem_u32(smem);
    const int tid  = threadIdx.x;
    const int lane = tid & 31;
    const int wid  = tid >> 5;
    int* s_item = (int*)(smem + CTRL);
    int* s_last = (int*)(smem + CTRL + 4);

    const int hw_id = tid >> 4, m = tid & 15;
    const int rowA  = lane & 15;
    const int acol0 = (lane >> 4) << 4;
    const int aswz  = (rowA & 7) << 4;
    const int rbA0  = (32 * wid + rowA) * 128;
    const int rbA1  = rbA0 + 16 * 128;
    const int rowB  = (lane & 7) + ((lane & 16) >> 1);
    const int bcol0 = (lane & 8) << 1;
    const int bswz  = (rowB & 7) << 4;
    const int rbB   = rowB * 128;
    const int r4 = lane >> 2, c2 = 2 * (lane & 3);

    for (;;) {
        __syncthreads();
        if (tid == 0) *s_item = atomicAdd(&g_q, 1);
        __syncthreads();
        int item = *s_item;
        if (item >= N_ITEMS) return;

        int K, kw, pad, co0, wt0, chunk, k0, klen, seg, nsegs, cidx;
        const float *off, *msk;
        float* pbase = 0;
        if (item < 512) {
            chunk = item >> 2; seg = item & 3;
            K = 49; kw = 7; pad = 3; co0 = 128; wt0 = 34;
            k0 = (seg == 0) ? 0 : (13 + 12 * (seg - 1));
            klen = (seg == 0) ? 13 : 12;
            nsegs = 4; cidx = chunk;
            off = off3; msk = m3;
            pbase = g_p3 + ((size_t)(seg * 128 + chunk)) * (64 * 128);
        } else if (item < 768) {
            int it = item - 512;
            chunk = it >> 1; seg = it & 1;
            K = 25; kw = 5; pad = 2; co0 = 64; wt0 = 9;
            k0 = (seg == 0) ? 0 : 13;
            klen = (seg == 0) ? 13 : 12;
            nsegs = 2; cidx = 128 + chunk;
            off = off2; msk = m2;
            pbase = g_p2 + ((size_t)(seg * 128 + chunk)) * (64 * 128);
        } else {
            chunk = item - 768; seg = 0;
            K = 9; kw = 3; pad = 1; co0 = 0; wt0 = 0;
            k0 = 0; klen = 9; nsegs = 1; cidx = 0;
            off = off1; msk = m1;
        }

        const int chunkPx0 = chunk << 7;
        const int b = chunkPx0 >> 12;
        const float* xtB = g_xt + (size_t)b * (64 * 64 * 64);
        const int pixl = (chunkPx0 + hw_id * 16 + m) & 4095;
        const int xo_own = pixl & 63, yo_own = pixl >> 6;
        const float* offB = off + (size_t)b * 2 * K * HW;
        const float* mskB = msk + (size_t)b * K * HW;

        float acc[2][8][4];
#pragma unroll
        for (int i = 0; i < 2; ++i)
#pragma unroll
            for (int j = 0; j < 8; ++j)
#pragma unroll
                for (int q = 0; q < 4; ++q) acc[i][j][q] = 0.f;

        for (int t = 0; t < klen; ++t) {
            const int k = k0 + t;
            __syncthreads();   // prev tap's mma done reading S/W

            // ---- W tile copy via cp.async (16KB) ----
            {
                const char* srcH = (const char*)(g_whimg + (size_t)(wt0 + k) * 4096) + tid * 16;
                const char* srcL = (const char*)(g_wlimg + (size_t)(wt0 + k) * 4096) + tid * 16;
                u32 dH = sb + WHOF + tid * 16;
                u32 dL = sb + WLOF + tid * 16;
#pragma unroll
                for (int i = 0; i < 4; ++i) {
                    CPA16(dH + i * 2048, srcH + i * 2048);
                    CPA16(dL + i * 2048, srcL + i * 2048);
                }
                asm volatile("cp.async.commit_group;");
            }

            // ---- per-thread bilinear setup for OWN pixel ----
            float w00, w01, w10, w11;
            u32 pk0, pk1;
            {
                const float* offY = offB + (size_t)(2 * k) * HW;
                const float* offX = offY + HW;
                const float* mk   = mskB + (size_t)k * HW;
                float dy = __ldg(offY + pixl);
                float dx = __ldg(offX + pixl);
                float mm = __ldg(mk + pixl);
                const int ky = k / kw, kx = k - ky * kw;
                float py  = (float)(yo_own - pad + ky) + dy;
                float pxx = (float)(xo_own - pad + kx) + dx;
                float fy = floorf(py), fx = floorf(pxx);
                float wy = py - fy,    wx = pxx - fx;
                int y0 = (int)fy, x0 = (int)fx;
                int y1 = y0 + 1,  x1 = x0 + 1;
                float vy0 = (y0 >= 0 && y0 < 64) ? 1.f : 0.f;
                float vy1 = (y1 >= 0 && y1 < 64) ? 1.f : 0.f;
                float vx0 = (x0 >= 0 && x0 < 64) ? 1.f : 0.f;
                float vx1 = (x1 >= 0 && x1 < 64) ? 1.f : 0.f;
                w00 = (1.f - wy) * (1.f - wx) * mm * vy0 * vx0;
                w01 = (1.f - wy) * wx         * mm * vy0 * vx1;
                w10 = wy         * (1.f - wx) * mm * vy1 * vx0;
                w11 = wy         * wx         * mm * vy1 * vx1;
                int cy0 = min(max(y0, 0), 63), cy1 = min(max(y1, 0), 63);
                int cx0 = min(max(x0, 0), 63), cx1 = min(max(x1, 0), 63);
                pk0 = ((u32)(cy0 * 64 + cx0) << 16) | (u32)(cy0 * 64 + cx1);
                pk1 = ((u32)(cy1 * 64 + cx0) << 16) | (u32)(cy1 * 64 + cx1);
            }

            // ---- gather loop: weights/indices broadcast via shfl ----
            {
                const float4* vp = (const float4*)xtB;
                const int sbase = lane & 16;
#pragma unroll 4
                for (int it = 0; it < 16; ++it) {
                    int src = sbase + it;
                    float W00 = __shfl_sync(0xffffffffu, w00, src);
                    float W01 = __shfl_sync(0xffffffffu, w01, src);
                    float W10 = __shfl_sync(0xffffffffu, w10, src);
                    float W11 = __shfl_sync(0xffffffffu, w11, src);
                    u32 P0 = __shfl_sync(0xffffffffu, pk0, src);
                    u32 P1 = __shfl_sync(0xffffffffu, pk1, src);

                    float4 v00 = vp[(P0 >> 16) * 16 + m];
                    float4 v01 = vp[(P0 & 0xffffu) * 16 + m];
                    float4 v10 = vp[(P1 >> 16) * 16 + m];
                    float4 v11 = vp[(P1 & 0xffffu) * 16 + m];

                    float s0 = fmaf(W00, v00.x, fmaf(W01, v01.x, fmaf(W10, v10.x, W11 * v11.x)));
                    float s1 = fmaf(W00, v00.y, fmaf(W01, v01.y, fmaf(W10, v10.y, W11 * v11.y)));
                    float s2 = fmaf(W00, v00.z, fmaf(W01, v01.z, fmaf(W10, v10.z, W11 * v11.z)));
                    float s3 = fmaf(W00, v00.w, fmaf(W01, v01.w, fmaf(W10, v10.w, W11 * v11.w)));

                    __nv_bfloat162 h01 = __floats2bfloat162_rn(s0, s1);
                    __nv_bfloat162 h23 = __floats2bfloat162_rn(s2, s3);
                    float2 f01 = __bfloat1622float2(h01);
                    float2 f23 = __bfloat1622float2(h23);
                    __nv_bfloat162 l01 = __floats2bfloat162_rn(s0 - f01.x, s1 - f01.y);
                    __nv_bfloat162 l23 = __floats2bfloat162_rn(s2 - f23.x, s3 - f23.y);

                    int px = hw_id * 16 + it;
                    int cb = px * 128 + ((8 * m) ^ ((px & 7) << 4));
                    *(uint2*)(smem + SH + cb) = make_uint2(*(u32*)&h01, *(u32*)&h23);
                    *(uint2*)(smem + SL + cb) = make_uint2(*(u32*)&l01, *(u32*)&l23);
                }
            }
            asm volatile("cp.async.wait_group 0;");
            __syncthreads();

            // ---- GEMM: 3-pass bf16 split, fp32 accum in registers ----
#pragma unroll
            for (int k4 = 0; k4 < 4; ++k4) {
                u32 colA = (u32)((32 * k4 + acol0) ^ aswz);
                u32 aH0[4], aH1[4], aL0[4], aL1[4];
                LDSM4(aH0, sb + SH + rbA0 + colA);
                LDSM4(aH1, sb + SH + rbA1 + colA);
                LDSM4(aL0, sb + SL + rbA0 + colA);
                LDSM4(aL1, sb + SL + rbA1 + colA);
                u32 colB = (u32)((32 * k4 + bcol0) ^ bswz);
#pragma unroll
                for (int p = 0; p < 4; ++p) {
                    u32 badr = (u32)(rbB + p * 2048) + colB;
                    u32 bH[4], bL[4];
                    LDSM4(bH, sb + WHOF + badr);
                    LDSM4(bL, sb + WLOF + badr);
                    MMA16(acc[0][2 * p],     aH0, bH[0], bH[1]);
                    MMA16(acc[1][2 * p],     aH1, bH[0], bH[1]);
                    MMA16(acc[0][2 * p + 1], aH0, bH[2], bH[3]);
                    MMA16(acc[1][2 * p + 1], aH1, bH[2], bH[3]);
                    MMA16(acc[0][2 * p],     aL0, bH[0], bH[1]);
                    MMA16(acc[1][2 * p],     aL1, bH[0], bH[1]);
                    MMA16(acc[0][2 * p + 1], aL0, bH[2], bH[3]);
                    MMA16(acc[1][2 * p + 1], aL1, bH[2], bH[3]);
                    MMA16(acc[0][2 * p],     aH0, bL[0], bL[1]);
                    MMA16(acc[1][2 * p],     aH1, bL[0], bL[1]);
                    MMA16(acc[0][2 * p + 1], aH0, bL[2], bL[3]);
                    MMA16(acc[1][2 * p + 1], aH1, bL[2], bL[3]);
                }
            }
        }

        // ---------------- epilogue ----------------
        if (nsegs == 1) {
            float* ob = out + (size_t)(b * 192 + co0) * HW;
#pragma unroll
            for (int mt = 0; mt < 2; ++mt) {
                int pxl = 32 * wid + 16 * mt + r4;
                int pix0 = (chunkPx0 + pxl) & 4095;
                int pix1 = (chunkPx0 + pxl + 8) & 4095;
#pragma unroll
                for (int nt = 0; nt < 8; ++nt) {
                    int co = 8 * nt + c2;
                    ob[(size_t)co * HW + pix0]       = acc[mt][nt][0];
                    ob[(size_t)(co + 1) * HW + pix0] = acc[mt][nt][1];
                    ob[(size_t)co * HW + pix1]       = acc[mt][nt][2];
                    ob[(size_t)(co + 1) * HW + pix1] = acc[mt][nt][3];
                }
            }
        } else {
#pragma unroll
            for (int mt = 0; mt < 2; ++mt) {
                int pxl = 32 * wid + 16 * mt + r4;
#pragma unroll
                for (int nt = 0; nt < 8; ++nt) {
                    int co = 8 * nt + c2;
                    pbase[co * 128 + pxl]           = acc[mt][nt][0];
                    pbase[(co + 1) * 128 + pxl]     = acc[mt][nt][1];
                    pbase[co * 128 + pxl + 8]       = acc[mt][nt][2];
                    pbase[(co + 1) * 128 + pxl + 8] = acc[mt][nt][3];
                }
            }
            __threadfence();
            __syncthreads();
            if (tid == 0)
                *s_last = (atomicAdd(&g_cnt[cidx], 1) == nsegs - 1) ? 1 : 0;
            __syncthreads();
            if (*s_last) {
                const float* basep = (nsegs == 4) ? g_p3 : g_p2;
                float* outB = out + (size_t)(b * 192 + co0) * HW + ((chunkPx0 + tid) & 4095);
                for (int co = 0; co < 64; ++co) {
                    float s = 0.f;
                    for (int sg = 0; sg < nsegs; ++sg)
                        s += basep[((size_t)(sg * 128 + chunk) * 64 + co) * 128 + tid];
                    outB[(size_t)co * HW] = s;
                }
            }
        }
    }
}

extern "C" void kernel_launch(void* const* d_in, const int* in_sizes, int n_in,
                              void* d_out, int out_size) {
    const float* x  = (const float*)d_in[0];
    const float* f1 = (const float*)d_in[1];
    const float* o1 = (const float*)d_in[2];
    const float* m1 = (const float*)d_in[3];
    const float* f2 = (const float*)d_in[4];
    const float* o2 = (const float*)d_in[5];
    const float* m2 = (const float*)d_in[6];
    const float* f3 = (const float*)d_in[7];
    const float* o3 = (const float*)d_in[8];
    const float* m3 = (const float*)d_in[9];
    float* out = (float*)d_out;

    cudaFuncSetAttribute(dcn_kernel, cudaFuncAttributeMaxDynamicSharedMemorySize, SMEM_BYTES);
    prep_kernel<<<1585, 256>>>(x, f1, f2, f3);
    dcn_kernel<<<444, 128, SMEM_BYTES>>>(o1, m1, o2, m2, o3, m3, out);
}